// round 15
// baseline (speedup 1.0000x reference)
#include <cuda_runtime.h>

#define BB 8
#define NN 16384
#define DD 768
#define CC 8
#define NCLS 2
#define D4 (DD/4)               // 192 float4 per row
#define BPB 296                 // blocks per bag
#define NBLK (BB*BPB)           // 2368 blocks = ~4 waves of 4x148 -> HW self-balancing
#define BTH 384
#define GROUPS 4
#define GTH 96                  // threads per group; thread owns cols (c, c+96)
#define RBASE (NN/BPB)          // 55
#define REXTRA (NN - RBASE*BPB) // 104 blocks get 56
#define RMAX 64
#define NW 2                    // warps covering RMAX rows

// Scratch (device globals — allocation-free per harness rules)
__device__ float g_plog[NBLK * CC * NCLS];   // per-block per-cluster logit partials
__device__ int   g_cntp[NBLK * CC];
__device__ int   g_bagdone[BB];              // per-bag completion counters (self-reset)

__global__ __launch_bounds__(BTH, 4)
void seg_sum_kernel(const float* __restrict__ inst, const int* __restrict__ labels,
                    const float* __restrict__ head_w, const float* __restrict__ head_b,
                    float* __restrict__ out) {
    // s_acc first and explicitly 16B-aligned: it is accessed as float4.
    __shared__ __align__(16) float s_acc[CC * DD];   // 24 KB
    __shared__ int   s_sorted[RMAX];
    __shared__ int   s_hist[NW][CC];
    __shared__ int   s_off[CC + 1];
    __shared__ int   s_cnt[CC];
    __shared__ float s_dot[CC][GTH/32][NCLS];        // per-cluster per-warp dot partials
    __shared__ int   s_isLast;
    __shared__ float s_red[CC * NCLS][24];           // finalize: strided partials
    __shared__ int   s_redc[CC][48];
    __shared__ float s_logits[CC][NCLS];
    __shared__ int   s_ctot[CC];

    const int t   = threadIdx.x;
    const int bag = blockIdx.x / BPB;
    const int bi  = blockIdx.x % BPB;
    const int rstart = bi * RBASE + (bi < REXTRA ? bi : REXTRA);
    const int R      = RBASE + (bi < REXTRA ? 1 : 0);       // 55 or 56

    // ---- L2 prefetch of this block's whole region (~43 KB) ----
    {
        const char* pf = (const char*)(inst + ((long)bag * NN + rstart) * DD);
        const char* p  = pf + (long)t * 128;                // 384*128B = 48KB >= region
        asm volatile("prefetch.global.L2 [%0];" :: "l"(p));
    }

    // ---- zero ----
    if (t < NW * CC) ((int*)s_hist)[t] = 0;
    {
        float4 z = make_float4(0.f, 0.f, 0.f, 0.f);
        float4* sa4 = reinterpret_cast<float4*>(s_acc);
        #pragma unroll
        for (int i = t; i < CC * D4; i += BTH) sa4[i] = z;
    }
    __syncthreads();

    // ---- deterministic counting sort of row indices by label ----
    int mylbl = -1, mypos = 0, myw = t >> 5;
    if (t < NW * 32) {
        mylbl = (t < R) ? labels[(long)bag * NN + rstart + t] : -1;
        unsigned mask = __match_any_sync(0xffffffffu, mylbl);
        int lane = t & 31;
        mypos = __popc(mask & ((1u << lane) - 1u));
        if (mylbl >= 0 && lane == (__ffs(mask) - 1))
            s_hist[myw][mylbl] = __popc(mask);
    }
    __syncthreads();
    if (t < CC) {                               // parallel column sums
        int c = 0;
        #pragma unroll
        for (int w = 0; w < NW; ++w) c += s_hist[w][t];
        s_cnt[t] = c;
    }
    __syncthreads();
    if (t == 0) {                               // short 8-step prefix
        int run = 0;
        #pragma unroll
        for (int l = 0; l < CC; ++l) { s_off[l] = run; run += s_cnt[l]; }
        s_off[CC] = run;
    }
    __syncthreads();
    if (mylbl >= 0) {
        int base = s_off[mylbl];
        #pragma unroll
        for (int w = 0; w < NW; ++w)
            if (w < myw) base += s_hist[w][mylbl];
        s_sorted[base + mypos] = t;             // local row index
    }
    __syncthreads();

    // ---- hot loop: each group walks a contiguous slice of the sorted list ----
    const int g   = t / GTH;                    // 0..3
    const int col = t % GTH;
    const int p0  = (R * g) / GROUPS;
    const int p1  = (R * (g + 1)) / GROUPS;

    const float4* __restrict__ base4 =
        reinterpret_cast<const float4*>(inst) + ((long)bag * NN + rstart) * D4;

    #pragma unroll
    for (int l = 0; l < CC; ++l) {
        int s = s_off[l]     > p0 ? s_off[l]     : p0;
        int e = s_off[l + 1] < p1 ? s_off[l + 1] : p1;
        if (s >= e) continue;

        float4 a0 = make_float4(0.f, 0.f, 0.f, 0.f);
        float4 a1 = make_float4(0.f, 0.f, 0.f, 0.f);
        int j = s;
        for (; j + 2 <= e; j += 2) {            // 4 LDG.128 in flight / thread
            int r0 = s_sorted[j];
            int r1 = s_sorted[j + 1];
            float4 v0 = __ldcs(&base4[(long)r0 * D4 + col]);
            float4 w0 = __ldcs(&base4[(long)r0 * D4 + col + GTH]);
            float4 v1 = __ldcs(&base4[(long)r1 * D4 + col]);
            float4 w1 = __ldcs(&base4[(long)r1 * D4 + col + GTH]);
            a0.x += v0.x; a0.y += v0.y; a0.z += v0.z; a0.w += v0.w;
            a1.x += w0.x; a1.y += w0.y; a1.z += w0.z; a1.w += w0.w;
            a0.x += v1.x; a0.y += v1.y; a0.z += v1.z; a0.w += v1.w;
            a1.x += w1.x; a1.y += w1.y; a1.z += w1.z; a1.w += w1.w;
        }
        if (j < e) {
            int r = s_sorted[j];
            float4 v = __ldcs(&base4[(long)r * D4 + col]);
            float4 w = __ldcs(&base4[(long)r * D4 + col + GTH]);
            a0.x += v.x; a0.y += v.y; a0.z += v.z; a0.w += v.w;
            a1.x += w.x; a1.y += w.y; a1.z += w.z; a1.w += w.w;
        }
        float* d0 = &s_acc[l * DD + col * 4];
        float* d1 = &s_acc[l * DD + (col + GTH) * 4];
        atomicAdd(d0 + 0, a0.x); atomicAdd(d0 + 1, a0.y);
        atomicAdd(d0 + 2, a0.z); atomicAdd(d0 + 3, a0.w);
        atomicAdd(d1 + 0, a1.x); atomicAdd(d1 + 1, a1.y);
        atomicAdd(d1 + 2, a1.z); atomicAdd(d1 + 3, a1.w);
    }
    __syncthreads();

    // ---- epilogue: dot block-partial sums with head_w -> 16 floats ----
    {
        const float4* sa = reinterpret_cast<const float4*>(s_acc);
        const float4* W  = reinterpret_cast<const float4*>(head_w);
        float4 u0 = W[col],      u1 = W[col + GTH];        // class 0 row
        float4 v0 = W[D4 + col], v1 = W[D4 + col + GTH];   // class 1 row
        #pragma unroll
        for (int c = g; c < CC; c += GROUPS) {
            float4 a0 = sa[c * D4 + col];
            float4 a1 = sa[c * D4 + col + GTH];
            float l0 = a0.x*u0.x + a0.y*u0.y + a0.z*u0.z + a0.w*u0.w
                     + a1.x*u1.x + a1.y*u1.y + a1.z*u1.z + a1.w*u1.w;
            float l1 = a0.x*v0.x + a0.y*v0.y + a0.z*v0.z + a0.w*v0.w
                     + a1.x*v1.x + a1.y*v1.y + a1.z*v1.z + a1.w*v1.w;
            #pragma unroll
            for (int o = 16; o > 0; o >>= 1) {
                l0 += __shfl_xor_sync(0xffffffff, l0, o);
                l1 += __shfl_xor_sync(0xffffffff, l1, o);
            }
            if ((col & 31) == 0) {
                s_dot[c][col >> 5][0] = l0;
                s_dot[c][col >> 5][1] = l1;
            }
        }
    }
    __syncthreads();
    if (t < CC * NCLS) {                         // 16 threads write logit partials
        int gg = t >> 1, cls = t & 1;
        float s = s_dot[gg][0][cls] + s_dot[gg][1][cls] + s_dot[gg][2][cls];
        g_plog[(blockIdx.x * CC + gg) * NCLS + cls] = s;
    }
    if (t < CC) g_cntp[blockIdx.x * CC + t] = s_cnt[t];

    // ---- last block per bag performs the finalize ----
    __threadfence();                             // publish this block's partials
    __syncthreads();                             // (cumulativity: all writers fenced-before)
    if (t == 0) {
        int old = atomicAdd(&g_bagdone[bag], 1);
        s_isLast = (old == BPB - 1) ? 1 : 0;
    }
    __syncthreads();

    if (s_isLast) {
        const float* plog = g_plog + (long)bag * BPB * CC * NCLS;
        const int*   cntp = g_cntp + (long)bag * BPB * CC;

        // strided-parallel reduce of 296 partials: 384 threads = 16 pairs x 24 parts
        {
            int pair = t % (CC * NCLS);          // (c, cls)
            int part = t / (CC * NCLS);          // 0..23
            int c = pair >> 1, cls = pair & 1;
            float acc = 0.0f;
            for (int k = part; k < BPB; k += 24)
                acc += __ldcg(&plog[(k * CC + c) * NCLS + cls]);
            s_red[pair][part] = acc;
        }
        {
            int c = t % CC;                      // 8 clusters x 48 parts
            int part = t / CC;                   // 0..47
            int acc = 0;
            for (int k = part; k < BPB; k += 48)
                acc += __ldcg(&cntp[k * CC + c]);
            s_redc[c][part] = acc;
        }
        __syncthreads();

        if (t < CC * NCLS) {
            float acc = 0.0f;
            #pragma unroll
            for (int p = 0; p < 24; ++p) acc += s_red[t][p];
            s_logits[t >> 1][t & 1] = acc;
        } else if (t >= 32 && t < 32 + CC) {
            int c = t - 32, acc = 0;
            #pragma unroll
            for (int p = 0; p < 48; ++p) acc += s_redc[c][p];
            s_ctot[c] = acc;
        }
        __syncthreads();

        if (t == 0) {
            float b0 = head_b[0], b1 = head_b[1];
            float best = -1e30f, bl0 = 0.f, bl1 = 0.f;
            #pragma unroll
            for (int c = 0; c < CC; ++c) {
                int cnt = s_ctot[c];
                float inv = 1.0f / (float)(cnt > 0 ? cnt : 1);
                float l0 = s_logits[c][0] * inv + b0;
                float l1 = s_logits[c][1] * inv + b1;
                float m  = fmaxf(l0, l1);
                float e0 = expf(l0 - m), e1 = expf(l1 - m);
                float score = 1.0f - e0 / (e0 + e1);   // 1 - p[nor_index=0]
                if (score > best) { best = score; bl0 = l0; bl1 = l1; }
            }
            out[bag * NCLS + 0] = bl0;
            out[bag * NCLS + 1] = bl1;
            g_bagdone[bag] = 0;                  // reset for next graph replay
        }
    }
}

extern "C" void kernel_launch(void* const* d_in, const int* in_sizes, int n_in,
                              void* d_out, int out_size) {
    const float* inst_feat = (const float*)d_in[0];   // [B, N, D] f32
    const int*   labels    = (const int*)  d_in[1];   // [B, N] i32
    const float* head_w    = (const float*)d_in[2];   // [NC, D] f32
    const float* head_b    = (const float*)d_in[3];   // [NC] f32
    float* out = (float*)d_out;                       // [B, NC] f32

    seg_sum_kernel<<<NBLK, BTH>>>(inst_feat, labels, head_w, head_b, out);
}

// round 16
// speedup vs baseline: 1.1223x; 1.1223x over previous
#include <cuda_runtime.h>

#define BB 8
#define NN 16384
#define DD 768
#define CC 8
#define NCLS 2
#define D4 (DD/4)               // 192 float4 per row
#define BPB 74                  // blocks per bag
#define NBLK (BB*BPB)           // 592 = 4 * 148 SMs, exactly one wave
#define BTH 384
#define GROUPS 4
#define GTH 96                  // threads per group; thread owns cols (c, c+96)
#define LPG (CC/GROUPS)         // 2 labels per group
#define RBASE (NN/BPB)          // 221
#define REXTRA (NN - RBASE*BPB) // 30 blocks get 222
#define RMAX 224
#define NW 7                    // warps covering RMAX rows

// Scratch (device globals — allocation-free per harness rules)
__device__ float g_plog[NBLK * CC * NCLS];   // per-block per-cluster logit partials
__device__ int   g_cntp[NBLK * CC];
__device__ int   g_bagdone[BB];              // per-bag completion counters (self-reset)

__global__ __launch_bounds__(BTH, 4)
void seg_sum_kernel(const float* __restrict__ inst, const int* __restrict__ labels,
                    const float* __restrict__ head_w, const float* __restrict__ head_b,
                    float* __restrict__ out) {
    __shared__ int   s_sorted[RMAX];
    __shared__ int   s_hist[NW][CC];
    __shared__ int   s_off[CC + 1];
    __shared__ int   s_cnt[CC];
    __shared__ int   s_pair[GROUPS][LPG];            // count-balanced label pairing
    __shared__ float s_dot[CC][GTH/32][NCLS];        // per-cluster per-warp dot partials
    __shared__ int   s_isLast;
    __shared__ float s_pl[BPB * CC * NCLS];          // last-block finalize buffers
    __shared__ int   s_pc[BPB * CC];
    __shared__ float s_logits[CC][NCLS];
    __shared__ int   s_ctot[CC];

    const int t   = threadIdx.x;
    const int bag = blockIdx.x / BPB;
    const int bi  = blockIdx.x % BPB;
    const int rstart = bi * RBASE + (bi < REXTRA ? bi : REXTRA);
    const int R      = RBASE + (bi < REXTRA ? 1 : 0);       // 221 or 222

    // ---- L2 prefetch: fill DRAM during the sort bubble ----
    {
        const char* pf = (const char*)(inst + ((long)bag * NN + rstart) * DD);
        #pragma unroll
        for (int k = 0; k < 4; ++k) {
            const char* p = pf + ((long)t + (long)k * BTH) * 128;   // 192 KB
            asm volatile("prefetch.global.L2 [%0];" :: "l"(p));
        }
    }

    // ---- zero hist ----
    if (t < NW * CC) ((int*)s_hist)[t] = 0;
    __syncthreads();

    // ---- deterministic counting sort of row indices by label ----
    int mylbl = -1, mypos = 0, myw = t >> 5;
    if (t < NW * 32) {
        mylbl = (t < R) ? labels[(long)bag * NN + rstart + t] : -1;
        unsigned mask = __match_any_sync(0xffffffffu, mylbl);
        int lane = t & 31;
        mypos = __popc(mask & ((1u << lane) - 1u));
        if (mylbl >= 0 && lane == (__ffs(mask) - 1))
            s_hist[myw][mylbl] = __popc(mask);
    }
    __syncthreads();
    if (t < CC) {                               // parallel column sums
        int c = 0;
        #pragma unroll
        for (int w = 0; w < NW; ++w) c += s_hist[w][t];
        s_cnt[t] = c;
    }
    __syncthreads();
    if (t == 0) {
        int run = 0;
        #pragma unroll
        for (int l = 0; l < CC; ++l) { s_off[l] = run; run += s_cnt[l]; }
        s_off[CC] = run;
        // rank labels by count (desc, ties by index) and pair big-with-small
        int ord[CC];
        #pragma unroll
        for (int i = 0; i < CC; ++i) ord[i] = i;
        #pragma unroll
        for (int i = 0; i < CC - 1; ++i)
            #pragma unroll
            for (int j = i + 1; j < CC; ++j)
                if (s_cnt[ord[j]] > s_cnt[ord[i]]) { int tmp = ord[i]; ord[i] = ord[j]; ord[j] = tmp; }
        #pragma unroll
        for (int gg = 0; gg < GROUPS; ++gg) {
            s_pair[gg][0] = ord[gg];
            s_pair[gg][1] = ord[CC - 1 - gg];
        }
    }
    __syncthreads();
    if (mylbl >= 0) {
        int base = s_off[mylbl];
        #pragma unroll
        for (int w = 0; w < NW; ++w)
            if (w < myw) base += s_hist[w][mylbl];
        s_sorted[base + mypos] = t;             // local row index
    }
    __syncthreads();

    // ---- hot loop: each group owns LPG whole clusters; pure register accumulation ----
    const int g   = t / GTH;                    // 0..3
    const int col = t % GTH;

    const float4* __restrict__ base4 =
        reinterpret_cast<const float4*>(inst) + ((long)bag * NN + rstart) * D4;
    const float4* __restrict__ W = reinterpret_cast<const float4*>(head_w);

    #pragma unroll
    for (int k = 0; k < LPG; ++k) {
        const int l = s_pair[g][k];
        const int s = s_off[l];
        const int e = s_off[l + 1];

        float4 a0 = make_float4(0.f, 0.f, 0.f, 0.f);
        float4 a1 = make_float4(0.f, 0.f, 0.f, 0.f);
        int j = s;
        for (; j + 2 <= e; j += 2) {            // 4 LDG.128 in flight / thread
            int r0 = s_sorted[j];
            int r1 = s_sorted[j + 1];
            float4 v0 = __ldcs(&base4[(long)r0 * D4 + col]);
            float4 w0 = __ldcs(&base4[(long)r0 * D4 + col + GTH]);
            float4 v1 = __ldcs(&base4[(long)r1 * D4 + col]);
            float4 w1 = __ldcs(&base4[(long)r1 * D4 + col + GTH]);
            a0.x += v0.x; a0.y += v0.y; a0.z += v0.z; a0.w += v0.w;
            a1.x += w0.x; a1.y += w0.y; a1.z += w0.z; a1.w += w0.w;
            a0.x += v1.x; a0.y += v1.y; a0.z += v1.z; a0.w += v1.w;
            a1.x += w1.x; a1.y += w1.y; a1.z += w1.z; a1.w += w1.w;
        }
        if (j < e) {
            int r = s_sorted[j];
            float4 v = __ldcs(&base4[(long)r * D4 + col]);
            float4 w = __ldcs(&base4[(long)r * D4 + col + GTH]);
            a0.x += v.x; a0.y += v.y; a0.z += v.z; a0.w += v.w;
            a1.x += w.x; a1.y += w.y; a1.z += w.z; a1.w += w.w;
        }

        // dot with head rows straight from registers (L1-resident W)
        float4 u0 = W[col],      u1 = W[col + GTH];        // class 0 row
        float4 v0 = W[D4 + col], v1 = W[D4 + col + GTH];   // class 1 row
        float l0 = a0.x*u0.x + a0.y*u0.y + a0.z*u0.z + a0.w*u0.w
                 + a1.x*u1.x + a1.y*u1.y + a1.z*u1.z + a1.w*u1.w;
        float l1 = a0.x*v0.x + a0.y*v0.y + a0.z*v0.z + a0.w*v0.w
                 + a1.x*v1.x + a1.y*v1.y + a1.z*v1.z + a1.w*v1.w;
        #pragma unroll
        for (int o = 16; o > 0; o >>= 1) {
            l0 += __shfl_xor_sync(0xffffffff, l0, o);
            l1 += __shfl_xor_sync(0xffffffff, l1, o);
        }
        if ((col & 31) == 0) {
            s_dot[l][col >> 5][0] = l0;
            s_dot[l][col >> 5][1] = l1;
        }
    }
    __syncthreads();
    if (t < CC * NCLS) {                         // 16 threads write logit partials
        int gg = t >> 1, cls = t & 1;
        float s = s_dot[gg][0][cls] + s_dot[gg][1][cls] + s_dot[gg][2][cls];
        g_plog[(blockIdx.x * CC + gg) * NCLS + cls] = s;
    }
    if (t < CC) g_cntp[blockIdx.x * CC + t] = s_cnt[t];

    // ---- last block per bag performs the finalize ----
    __threadfence();                             // publish this block's partials
    __syncthreads();
    if (t == 0) {
        int old = atomicAdd(&g_bagdone[bag], 1);
        s_isLast = (old == BPB - 1) ? 1 : 0;
    }
    __syncthreads();

    if (s_isLast) {
        const float* plog = g_plog + (long)bag * BPB * CC * NCLS;
        const int*   cntp = g_cntp + (long)bag * BPB * CC;
        for (int i = t; i < BPB * CC * NCLS; i += BTH) s_pl[i] = __ldcg(&plog[i]);
        for (int i = t; i < BPB * CC; i += BTH)        s_pc[i] = __ldcg(&cntp[i]);
        __syncthreads();

        if (t < CC * NCLS) {                     // 16 threads: one (cluster, class)
            int c = t >> 1, cls = t & 1;
            float acc = 0.0f;
            #pragma unroll
            for (int k = 0; k < BPB; ++k) acc += s_pl[(k * CC + c) * NCLS + cls];
            s_logits[c][cls] = acc;
        } else if (t >= 32 && t < 32 + CC) {     // 8 threads: one cluster count
            int c = t - 32;
            int cnt = 0;
            #pragma unroll
            for (int k = 0; k < BPB; ++k) cnt += s_pc[k * CC + c];
            s_ctot[c] = cnt;
        }
        __syncthreads();

        if (t == 0) {
            float b0 = head_b[0], b1 = head_b[1];
            float best = -1e30f, bl0 = 0.f, bl1 = 0.f;
            #pragma unroll
            for (int c = 0; c < CC; ++c) {
                int cnt = s_ctot[c];
                float inv = 1.0f / (float)(cnt > 0 ? cnt : 1);
                float l0 = s_logits[c][0] * inv + b0;
                float l1 = s_logits[c][1] * inv + b1;
                float m  = fmaxf(l0, l1);
                float e0 = expf(l0 - m), e1 = expf(l1 - m);
                float score = 1.0f - e0 / (e0 + e1);   // 1 - p[nor_index=0]
                if (score > best) { best = score; bl0 = l0; bl1 = l1; }
            }
            out[bag * NCLS + 0] = bl0;
            out[bag * NCLS + 1] = bl1;
            g_bagdone[bag] = 0;                  // reset for next graph replay
        }
    }
}

extern "C" void kernel_launch(void* const* d_in, const int* in_sizes, int n_in,
                              void* d_out, int out_size) {
    const float* inst_feat = (const float*)d_in[0];   // [B, N, D] f32
    const int*   labels    = (const int*)  d_in[1];   // [B, N] i32
    const float* head_w    = (const float*)d_in[2];   // [NC, D] f32
    const float* head_b    = (const float*)d_in[3];   // [NC] f32
    float* out = (float*)d_out;                       // [B, NC] f32

    seg_sum_kernel<<<NBLK, BTH>>>(inst_feat, labels, head_w, head_b, out);
}

// round 17
// speedup vs baseline: 1.1700x; 1.0425x over previous
#include <cuda_runtime.h>

#define BB 8
#define NN 16384
#define DD 768
#define CC 8
#define NCLS 2
#define D4 (DD/4)               // 192 float4 per row
#define BPB 74                  // blocks per bag
#define NBLK (BB*BPB)           // 592 = 4 * 148 SMs, exactly one wave
#define BTH 384
#define GROUPS 4
#define GTH 96                  // threads per group; thread owns cols (c, c+96)
#define RBASE (NN/BPB)          // 221
#define REXTRA (NN - RBASE*BPB) // 30 blocks get 222
#define RMAX 224
#define NW 7                    // warps covering RMAX rows

// Scratch (device globals — allocation-free per harness rules)
__device__ float g_plog[NBLK * CC * NCLS];   // per-block per-cluster logit partials
__device__ int   g_cntp[NBLK * CC];
__device__ int   g_bagdone[BB];              // per-bag completion counters (self-reset)

__global__ __launch_bounds__(BTH, 4)
void seg_sum_kernel(const float* __restrict__ inst, const int* __restrict__ labels,
                    const float* __restrict__ head_w, const float* __restrict__ head_b,
                    float* __restrict__ out) {
    __shared__ int   s_sorted[RMAX];
    __shared__ int   s_hist[NW][CC];
    __shared__ int   s_off[CC + 1];
    __shared__ int   s_cnt[CC];
    __shared__ float s_dot[CC][NCLS];                // logit accumulators
    __shared__ int   s_isLast;
    __shared__ float s_pl[BPB * CC * NCLS];          // last-block finalize buffers
    __shared__ int   s_pc[BPB * CC];
    __shared__ float s_logits[CC][NCLS];
    __shared__ int   s_ctot[CC];

    const int t   = threadIdx.x;
    const int bag = blockIdx.x / BPB;
    const int bi  = blockIdx.x % BPB;
    const int rstart = bi * RBASE + (bi < REXTRA ? bi : REXTRA);
    const int R      = RBASE + (bi < REXTRA ? 1 : 0);       // 221 or 222

    // ---- L2 prefetch: fill DRAM during the sort bubble ----
    {
        const char* pf = (const char*)(inst + ((long)bag * NN + rstart) * DD);
        #pragma unroll
        for (int k = 0; k < 4; ++k) {
            const char* p = pf + ((long)t + (long)k * BTH) * 128;   // 192 KB
            asm volatile("prefetch.global.L2 [%0];" :: "l"(p));
        }
    }

    // ---- zero ----
    if (t < NW * CC) ((int*)s_hist)[t] = 0;
    if (t < CC * NCLS) ((float*)s_dot)[t] = 0.0f;
    __syncthreads();

    // ---- deterministic counting sort of row indices by label ----
    int mylbl = -1, mypos = 0, myw = t >> 5;
    if (t < NW * 32) {
        mylbl = (t < R) ? labels[(long)bag * NN + rstart + t] : -1;
        unsigned mask = __match_any_sync(0xffffffffu, mylbl);
        int lane = t & 31;
        mypos = __popc(mask & ((1u << lane) - 1u));
        if (mylbl >= 0 && lane == (__ffs(mask) - 1))
            s_hist[myw][mylbl] = __popc(mask);
    }
    __syncthreads();
    if (t < CC) {                               // parallel column sums
        int c = 0;
        #pragma unroll
        for (int w = 0; w < NW; ++w) c += s_hist[w][t];
        s_cnt[t] = c;
    }
    __syncthreads();
    if (t == 0) {                               // short 8-step prefix
        int run = 0;
        #pragma unroll
        for (int l = 0; l < CC; ++l) { s_off[l] = run; run += s_cnt[l]; }
        s_off[CC] = run;
    }
    __syncthreads();
    if (mylbl >= 0) {
        int base = s_off[mylbl];
        #pragma unroll
        for (int w = 0; w < NW; ++w)
            if (w < myw) base += s_hist[w][mylbl];
        s_sorted[base + mypos] = t;             // local row index
    }
    __syncthreads();

    // ---- hot loop: each group walks a contiguous slice of the sorted list;
    //      per-run register accumulate, then fold into head dot immediately ----
    const int g   = t / GTH;                    // 0..3
    const int col = t % GTH;
    const int p0  = (R * g) / GROUPS;
    const int p1  = (R * (g + 1)) / GROUPS;

    const float4* __restrict__ base4 =
        reinterpret_cast<const float4*>(inst) + ((long)bag * NN + rstart) * D4;
    const float4* __restrict__ W = reinterpret_cast<const float4*>(head_w);

    #pragma unroll
    for (int l = 0; l < CC; ++l) {
        int s = s_off[l]     > p0 ? s_off[l]     : p0;
        int e = s_off[l + 1] < p1 ? s_off[l + 1] : p1;
        if (s >= e) continue;

        float4 a0 = make_float4(0.f, 0.f, 0.f, 0.f);
        float4 a1 = make_float4(0.f, 0.f, 0.f, 0.f);
        int j = s;
        for (; j + 2 <= e; j += 2) {            // 4 LDG.128 in flight / thread
            int r0 = s_sorted[j];
            int r1 = s_sorted[j + 1];
            float4 v0 = __ldcs(&base4[(long)r0 * D4 + col]);
            float4 w0 = __ldcs(&base4[(long)r0 * D4 + col + GTH]);
            float4 v1 = __ldcs(&base4[(long)r1 * D4 + col]);
            float4 w1 = __ldcs(&base4[(long)r1 * D4 + col + GTH]);
            a0.x += v0.x; a0.y += v0.y; a0.z += v0.z; a0.w += v0.w;
            a1.x += w0.x; a1.y += w0.y; a1.z += w0.z; a1.w += w0.w;
            a0.x += v1.x; a0.y += v1.y; a0.z += v1.z; a0.w += v1.w;
            a1.x += w1.x; a1.y += w1.y; a1.z += w1.z; a1.w += w1.w;
        }
        if (j < e) {
            int r = s_sorted[j];
            float4 v = __ldcs(&base4[(long)r * D4 + col]);
            float4 w = __ldcs(&base4[(long)r * D4 + col + GTH]);
            a0.x += v.x; a0.y += v.y; a0.z += v.z; a0.w += v.w;
            a1.x += w.x; a1.y += w.y; a1.z += w.z; a1.w += w.w;
        }

        // fold run-partial into head dot (W is L1-resident after first touch)
        float4 u0 = W[col],      u1 = W[col + GTH];        // class 0 row
        float4 v0 = W[D4 + col], v1 = W[D4 + col + GTH];   // class 1 row
        float l0 = a0.x*u0.x + a0.y*u0.y + a0.z*u0.z + a0.w*u0.w
                 + a1.x*u1.x + a1.y*u1.y + a1.z*u1.z + a1.w*u1.w;
        float l1 = a0.x*v0.x + a0.y*v0.y + a0.z*v0.z + a0.w*v0.w
                 + a1.x*v1.x + a1.y*v1.y + a1.z*v1.z + a1.w*v1.w;
        #pragma unroll
        for (int o = 16; o > 0; o >>= 1) {
            l0 += __shfl_xor_sync(0xffffffff, l0, o);
            l1 += __shfl_xor_sync(0xffffffff, l1, o);
        }
        if ((col & 31) == 0) {                  // 2 smem atomics per warp per run
            atomicAdd(&s_dot[l][0], l0);
            atomicAdd(&s_dot[l][1], l1);
        }
    }
    __syncthreads();
    if (t < CC * NCLS) {                         // 16 threads write logit partials
        int gg = t >> 1, cls = t & 1;
        g_plog[(blockIdx.x * CC + gg) * NCLS + cls] = s_dot[gg][cls];
    }
    if (t < CC) g_cntp[blockIdx.x * CC + t] = s_cnt[t];

    // ---- last block per bag performs the finalize ----
    __threadfence();                             // publish this block's partials
    __syncthreads();
    if (t == 0) {
        int old = atomicAdd(&g_bagdone[bag], 1);
        s_isLast = (old == BPB - 1) ? 1 : 0;
    }
    __syncthreads();

    if (s_isLast) {
        const float* plog = g_plog + (long)bag * BPB * CC * NCLS;
        const int*   cntp = g_cntp + (long)bag * BPB * CC;
        for (int i = t; i < BPB * CC * NCLS; i += BTH) s_pl[i] = __ldcg(&plog[i]);
        for (int i = t; i < BPB * CC; i += BTH)        s_pc[i] = __ldcg(&cntp[i]);
        __syncthreads();

        if (t < CC * NCLS) {                     // 16 threads: one (cluster, class)
            int c = t >> 1, cls = t & 1;
            float acc = 0.0f;
            #pragma unroll
            for (int k = 0; k < BPB; ++k) acc += s_pl[(k * CC + c) * NCLS + cls];
            s_logits[c][cls] = acc;
        } else if (t >= 32 && t < 32 + CC) {     // 8 threads: one cluster count
            int c = t - 32;
            int cnt = 0;
            #pragma unroll
            for (int k = 0; k < BPB; ++k) cnt += s_pc[k * CC + c];
            s_ctot[c] = cnt;
        }
        __syncthreads();

        if (t == 0) {
            float b0 = head_b[0], b1 = head_b[1];
            float best = -1e30f, bl0 = 0.f, bl1 = 0.f;
            #pragma unroll
            for (int c = 0; c < CC; ++c) {
                int cnt = s_ctot[c];
                float inv = 1.0f / (float)(cnt > 0 ? cnt : 1);
                float l0 = s_logits[c][0] * inv + b0;
                float l1 = s_logits[c][1] * inv + b1;
                float m  = fmaxf(l0, l1);
                float e0 = expf(l0 - m), e1 = expf(l1 - m);
                float score = 1.0f - e0 / (e0 + e1);   // 1 - p[nor_index=0]
                if (score > best) { best = score; bl0 = l0; bl1 = l1; }
            }
            out[bag * NCLS + 0] = bl0;
            out[bag * NCLS + 1] = bl1;
            g_bagdone[bag] = 0;                  // reset for next graph replay
        }
    }
}

extern "C" void kernel_launch(void* const* d_in, const int* in_sizes, int n_in,
                              void* d_out, int out_size) {
    const float* inst_feat = (const float*)d_in[0];   // [B, N, D] f32
    const int*   labels    = (const int*)  d_in[1];   // [B, N] i32
    const float* head_w    = (const float*)d_in[2];   // [NC, D] f32
    const float* head_b    = (const float*)d_in[3];   // [NC] f32
    float* out = (float*)d_out;                       // [B, NC] f32

    seg_sum_kernel<<<NBLK, BTH>>>(inst_feat, labels, head_w, head_b, out);
}